// round 17
// baseline (speedup 1.0000x reference)
#include <cuda_runtime.h>

#define NU 100000
#define NI 50000
#define NN 150000
#define HD 64
#define NE 1200000
#define SCAN_B 1024
#define NBLK ((NN + SCAN_B - 1) / SCAN_B)   // 147
#define EB   ((NE + 255) / 256)             // fill edge blocks (4688)
#define PB   ((NN * 16 + 255) / 256)        // prescale blocks (9375)

typedef unsigned long long ull;

// Scratch (static device globals; zero-initialized at load).
// bufA/bufB/v1/dinv have a zero slot at index NN (never written): padding.
__device__ __align__(16) float g_bufA[(NN + 1) * HD];
__device__ __align__(16) float g_bufB[(NN + 1) * HD];
__device__ float g_u1[NN];
__device__ float g_v1[NN + 1];
__device__ float g_u2[NN];
__device__ float g_dinv[NN + 1];
__device__ int   g_cnt[NN];
__device__ int   g_flag[NBLK];
__device__ int   g_off[NN + 1];
__device__ int   g_cur[NN];
__device__ int   g_edge[NE];
__device__ float g_W123[HD * HD];
__device__ float g_bv1[HD];
__device__ float g_bv2[HD];

#define FMA2(acc, a, b) \
    asm("fma.rn.f32x2 %0, %1, %2, %0;" : "+l"(acc) : "l"(a), "l"(b))
#define MUL2(d, a, b) \
    asm("mul.rn.f32x2 %0, %1, %2;" : "=l"(d) : "l"(a), "l"(b))
#define ADD2(acc, b) \
    asm("add.rn.f32x2 %0, %0, %1;" : "+l"(acc) : "l"(b))
#define DUPF(d, f) \
    asm("mov.b64 %0, {%1, %1};" : "=l"(d) : "f"(f))

// ---------------------------------------------------------------------------
__global__ void k_deg(const int* __restrict__ ei) {
    int e = blockIdx.x * blockDim.x + threadIdx.x;
    if (e < NE) atomicAdd(&g_cnt[ei[NE + e]], 1);
}

// ---------------------------------------------------------------------------
// Fused: blocks 0..NBLK-1 = single-pass scan of g_cnt + dinv;
// block NBLK = weight/bias products.
// ---------------------------------------------------------------------------
__global__ void __launch_bounds__(1024)
k_scan_wprod(const float* __restrict__ Wsrc, const float* __restrict__ bs) {
    __shared__ float smem[3 * 4096 + 64];
    int tid = threadIdx.x;

    if (blockIdx.x < NBLK) {
        int* ws    = (int*)smem;
        int* basep = (int*)smem + 40;
        if (tid == 0) *basep = 0;
        int i = blockIdx.x * SCAN_B + tid;
        int lane = tid & 31, wid = tid >> 5;
        int cnt = (i < NN) ? g_cnt[i] : 0;
        if (i < NN) g_dinv[i] = rsqrtf((float)(cnt + 1));
        int x = cnt;
        #pragma unroll
        for (int o = 1; o < 32; o <<= 1) {
            int y = __shfl_up_sync(0xffffffffu, x, o);
            if (lane >= o) x += y;
        }
        if (lane == 31) ws[wid] = x;
        __syncthreads();
        if (wid == 0) {
            int s = ws[lane];
            #pragma unroll
            for (int o = 1; o < 32; o <<= 1) {
                int y = __shfl_up_sync(0xffffffffu, s, o);
                if (lane >= o) s += y;
            }
            ws[lane] = s;
        }
        __syncthreads();
        int incl = x + (wid > 0 ? ws[wid - 1] : 0);

        if (tid == SCAN_B - 1)
            *((volatile int*)&g_flag[blockIdx.x]) = incl + 1;

        if (tid < blockIdx.x) {
            int v;
            do { v = *((volatile int*)&g_flag[tid]); } while (v == 0);
            atomicAdd(basep, v - 1);
        }
        __syncthreads();

        if (i < NN) {
            int g = incl + *basep;
            g_off[i + 1] = g;
            g_cur[i] = g - cnt;
            if (i == 0) g_off[0] = 0;
        }
    } else {
        float* A = smem;
        float* B = smem + 4096;
        float* T = smem + 8192;
        ((float4*)A)[tid] = ((const float4*)(Wsrc + 4096))[tid];   // W2
        ((float4*)B)[tid] = ((const float4*)(Wsrc + 8192))[tid];   // W3
        __syncthreads();
        #pragma unroll
        for (int i = 0; i < 4; i++) {            // T = W2@W3
            int idx = tid * 4 + i, r = idx >> 6, c = idx & 63;
            float s = 0.f;
            #pragma unroll
            for (int k = 0; k < 64; k++) s += A[r * 64 + k] * B[k * 64 + c];
            T[idx] = s;
        }
        __syncthreads();
        ((float4*)A)[tid] = ((const float4*)Wsrc)[tid];            // W1
        __syncthreads();
        #pragma unroll
        for (int i = 0; i < 4; i++) {            // W123 = W1@T
            int idx = tid * 4 + i, r = idx >> 6, c = idx & 63;
            float s = 0.f;
            #pragma unroll
            for (int k = 0; k < 64; k++) s += A[r * 64 + k] * T[k * 64 + c];
            g_W123[idx] = s;
        }
        if (tid < 64) {                          // bv2 = b1@T
            float s = 0.f;
            #pragma unroll
            for (int k = 0; k < 64; k++) s += bs[k] * T[k * 64 + tid];
            g_bv2[tid] = s;
        } else if (tid < 128) {                  // bv1 = b2@W3
            int c = tid - 64;
            float s = 0.f;
            #pragma unroll
            for (int k = 0; k < 64; k++) s += bs[64 + k] * B[k * 64 + c];
            g_bv1[c] = s;
        }
    }
}

// ---------------------------------------------------------------------------
// Fused: blocks [0, EB) = bucket fill; blocks [EB, EB+PB) = z0 prescale
//   z0[n] = dinv_n * concat(ue, ie)[n]   (written to bufB)
// ---------------------------------------------------------------------------
__global__ void k_fill(const int* __restrict__ ei,
                       const float* __restrict__ ue, const float* __restrict__ ie,
                       float* __restrict__ z0) {
    if (blockIdx.x < EB) {
        int e = blockIdx.x * blockDim.x + threadIdx.x;
        if (e >= NE) return;
        int s = ei[e];
        int d = ei[NE + e];
        int pos = atomicAdd(&g_cur[d], 1);
        g_edge[pos] = s;
    } else {
        int t = (blockIdx.x - EB) * blockDim.x + threadIdx.x;
        if (t >= NN * 16) return;
        int node = t >> 4, c = t & 15;
        float dv = g_dinv[node];
        const float4* src = (node < NU) ? (const float4*)&ue[(size_t)node * 64]
                                        : (const float4*)&ie[(size_t)(node - NU) * 64];
        float4 v = src[c];
        v.x *= dv; v.y *= dv; v.z *= dv; v.w *= dv;
        ((float4*)&z0[(size_t)node * 64])[c] = v;
    }
}

// ---------------------------------------------------------------------------
// agg1 (16 lanes/node, unweighted on z0):
//   z1[d] = dv_d^2 (sum z0[s] + z0[d]);  u1 = dv(sum dv_s + dv), v1 = dv*u1
// Padding edges -> zero row NN (exact no-op); g_dinv[NN]=0.
// ---------------------------------------------------------------------------
__global__ void __launch_bounds__(256, 8)
k_agg1(const float* __restrict__ x, float* __restrict__ y) {
    int t = blockIdx.x * blockDim.x + threadIdx.x;
    int node = t >> 4;
    int c = t & 15;
    if (node >= NN) return;
    unsigned gmask = 0xFFFFu << (threadIdx.x & 16);

    int beg = g_off[node];
    int end = g_off[node + 1];
    float dv = rsqrtf((float)(end - beg + 1));

    ulonglong2 s0 = *(const ulonglong2*)(x + (size_t)node * 64 + c * 4);
    ull a0 = s0.x, a1 = s0.y;
    float uacc = 0.0f;

    int idx = beg + (c & 7);
    int ed = (idx < end) ? g_edge[idx] : NN;
    for (int j0 = beg; j0 < end; j0 += 8) {
        int nidx = j0 + 8 + (c & 7);
        int edn = (nidx < end) ? g_edge[nidx] : NN;
        if (c < 8) uacc += g_dinv[ed];        // dinv[NN] == 0
        #pragma unroll
        for (int k = 0; k < 8; k++) {
            int s = __shfl_sync(gmask, ed, k, 16);
            ulonglong2 h = *(const ulonglong2*)(x + (size_t)s * 64 + c * 4);
            ADD2(a0, h.x); ADD2(a1, h.y);
        }
        ed = edn;
    }

    float dv2 = dv * dv;
    ull pdv2; DUPF(pdv2, dv2);
    MUL2(a0, a0, pdv2); MUL2(a1, a1, pdv2);
    *(ulonglong2*)(y + (size_t)node * 64 + c * 4) = make_ulonglong2(a0, a1);

    #pragma unroll
    for (int o = 8; o > 0; o >>= 1)
        uacc += __shfl_down_sync(gmask, uacc, o, 16);
    if (c == 0) {
        float u1 = dv * (uacc + dv);
        g_u1[node] = u1;
        g_v1[node] = dv * u1;
    }
}

// ---------------------------------------------------------------------------
// agg2 (16 lanes/node): z2[d] = dv_d^2 (sum z1[s] + z1[d]); u2 alongside.
// ---------------------------------------------------------------------------
__global__ void __launch_bounds__(256, 8)
k_agg2(const float* __restrict__ x, float* __restrict__ y) {
    int t = blockIdx.x * blockDim.x + threadIdx.x;
    int node = t >> 4;
    int c = t & 15;
    if (node >= NN) return;
    unsigned gmask = 0xFFFFu << (threadIdx.x & 16);

    int beg = g_off[node];
    int end = g_off[node + 1];
    float dv = rsqrtf((float)(end - beg + 1));

    ulonglong2 s0 = *(const ulonglong2*)(x + (size_t)node * 64 + c * 4);
    ull a0 = s0.x, a1 = s0.y;
    float uacc = 0.0f;

    int idx = beg + (c & 7);
    int ed = (idx < end) ? g_edge[idx] : NN;
    for (int j0 = beg; j0 < end; j0 += 8) {
        int nidx = j0 + 8 + (c & 7);
        int edn = (nidx < end) ? g_edge[nidx] : NN;
        if (c < 8) uacc += g_v1[ed];          // v1[NN] == 0
        #pragma unroll
        for (int k = 0; k < 8; k++) {
            int s = __shfl_sync(gmask, ed, k, 16);
            ulonglong2 h = *(const ulonglong2*)(x + (size_t)s * 64 + c * 4);
            ADD2(a0, h.x); ADD2(a1, h.y);
        }
        ed = edn;
    }

    float dv2 = dv * dv;
    ull pdv2; DUPF(pdv2, dv2);
    MUL2(a0, a0, pdv2); MUL2(a1, a1, pdv2);
    *(ulonglong2*)(y + (size_t)node * 64 + c * 4) = make_ulonglong2(a0, a1);

    #pragma unroll
    for (int o = 8; o > 0; o >>= 1)
        uacc += __shfl_down_sync(gmask, uacc, o, 16);
    if (c == 0) g_u2[node] = dv * (uacc + g_v1[node]);
}

// ---------------------------------------------------------------------------
// Fused agg3 + final GEMM (512 threads = 32 nodes x 16 lanes for agg):
//   y3[d] = dv_d (sum z2[s] + z2[d]) staged in smem.
// GEMM phase: 256 threads, 8 lanes x 8 cols (halved smem W traffic):
//   out[remap] = y3@W123 + u2*bv2 + u1*bv1 + b3.
// Also copies raw embeddings to out segments 1/3 and re-zeroes g_cnt/g_flag.
// ---------------------------------------------------------------------------
__global__ void __launch_bounds__(512)
k_agg_gemm(const float* __restrict__ x, const float* __restrict__ b3,
           const float* __restrict__ ue, const float* __restrict__ ie,
           float* __restrict__ out) {
    __shared__ float sW[64 * 64];
    __shared__ float sX[32 * 68];
    int tid  = threadIdx.x;
    int r = tid >> 4;          // 0..31
    int c = tid & 15;          // 0..15
    int node = blockIdx.x * 32 + r;
    unsigned gmask = 0xFFFFu << (tid & 16);

    #pragma unroll
    for (int i = 0; i < 2; i++)
        ((float4*)sW)[tid + i * 512] = ((const float4*)g_W123)[tid + i * 512];

    if (blockIdx.x == 0 && tid < NBLK) g_flag[tid] = 0;

    if (node < NN) {
        int beg = g_off[node];
        int end = g_off[node + 1];
        float dv = rsqrtf((float)(end - beg + 1));

        ulonglong2 s0 = *(const ulonglong2*)(x + (size_t)node * 64 + c * 4);
        ull a0 = s0.x, a1 = s0.y;

        int idx = beg + (c & 7);
        int ed = (idx < end) ? g_edge[idx] : NN;
        for (int j0 = beg; j0 < end; j0 += 8) {
            int nidx = j0 + 8 + (c & 7);
            int edn = (nidx < end) ? g_edge[nidx] : NN;
            #pragma unroll
            for (int k = 0; k < 8; k++) {
                int s = __shfl_sync(gmask, ed, k, 16);
                ulonglong2 h = *(const ulonglong2*)(x + (size_t)s * 64 + c * 4);
                ADD2(a0, h.x); ADD2(a1, h.y);
            }
            ed = edn;
        }
        ull pdv; DUPF(pdv, dv);
        MUL2(a0, a0, pdv); MUL2(a1, a1, pdv);
        *(ulonglong2*)&sX[r * 68 + c * 4] = make_ulonglong2(a0, a1);

        // embedding passthrough + state re-zero
        if (c == 0) g_cnt[node] = 0;
        const float4* src = (node < NU) ? (const float4*)&ue[(size_t)node * 64]
                                        : (const float4*)&ie[(size_t)(node - NU) * 64];
        size_t drow = (node < NU) ? (size_t)(NU + node)
                                  : (size_t)(2 * NU + NI + (node - NU));
        ((float4*)&out[drow * 64])[c] = src[c];
    }
    __syncthreads();

    // ---- GEMM phase: 256 threads, thread -> (row tid>>3, cols (tid&7)*8..+7)
    if (tid < 256) {
        int gr = tid >> 3;                 // 0..31
        int gnode = blockIdx.x * 32 + gr;
        int cb = (tid & 7) << 3;           // 0,8,...,56

        ull acc[4];
        {
            float un1 = (gnode < NN) ? g_u1[gnode] : 0.f;
            float un2 = (gnode < NN) ? g_u2[gnode] : 0.f;
            #pragma unroll
            for (int i = 0; i < 4; i++) {
                float lo = b3[cb + 2 * i]     + un2 * g_bv2[cb + 2 * i]     + un1 * g_bv1[cb + 2 * i];
                float hi = b3[cb + 2 * i + 1] + un2 * g_bv2[cb + 2 * i + 1] + un1 * g_bv1[cb + 2 * i + 1];
                asm("mov.b64 %0, {%1, %2};" : "=l"(acc[i]) : "f"(lo), "f"(hi));
            }
        }
        #pragma unroll
        for (int k = 0; k < 64; k++) {
            float xv = sX[gr * 68 + k];
            ull xvv; DUPF(xvv, xv);
            const ulonglong2* wp = (const ulonglong2*)&sW[k * 64 + cb];
            ulonglong2 wa = wp[0], wb2 = wp[1];
            FMA2(acc[0], xvv, wa.x);
            FMA2(acc[1], xvv, wa.y);
            FMA2(acc[2], xvv, wb2.x);
            FMA2(acc[3], xvv, wb2.y);
        }
        if (gnode < NN) {
            int orow = (gnode < NU) ? gnode : gnode + NU;
            ulonglong2* o = (ulonglong2*)&out[(size_t)orow * 64 + cb];
            o[0] = make_ulonglong2(acc[0], acc[1]);
            o[1] = make_ulonglong2(acc[2], acc[3]);
        }
    }
}

// ---------------------------------------------------------------------------
extern "C" void kernel_launch(void* const* d_in, const int* in_sizes, int n_in,
                              void* d_out, int out_size) {
    const int*   ei = (const int*)d_in[0];
    const float* ue = (const float*)d_in[1];
    const float* ie = (const float*)d_in[2];
    const float* Ws = (const float*)d_in[3];
    const float* bs = (const float*)d_in[4];
    float* out = (float*)d_out;

    float *bufA, *bufB;
    cudaGetSymbolAddress((void**)&bufA, g_bufA);
    cudaGetSymbolAddress((void**)&bufB, g_bufB);

    const int TB = 256;
    const int AGG_GRID = (NN * 16 + TB - 1) / TB;   // 9375
    k_deg       <<<(NE + TB - 1) / TB, TB>>>(ei);                           // 1
    k_scan_wprod<<<NBLK + 1, SCAN_B>>>(Ws, bs);                             // 2
    k_fill      <<<EB + PB, TB>>>(ei, ue, ie, bufB);                        // 3 (fill + z0 prescale)
    k_agg1      <<<AGG_GRID, TB>>>(bufB, bufA);                             // 4 <- profiled
    k_agg2      <<<AGG_GRID, TB>>>(bufA, bufB);                             // 5
    k_agg_gemm  <<<(NN + 31) / 32, 512>>>(bufB, bs + 2 * 64, ue, ie, out);  // 6
}